// round 14
// baseline (speedup 1.0000x reference)
#include <cuda_runtime.h>
#include <cuda_fp16.h>
#include <math.h>
#include <stdint.h>

// Shapes (fixed): B=2048, D=128, H=512
#define BATCH 2048
#define DDIM  128
#define HDIM  512

// ---------------- device scratch (static; no allocations) ----------------
__device__ float g_ench [BATCH * HDIM];                  // 4 MB
__device__ float g_enc  [BATCH * DDIM];                  // 1 MB
__device__ __half g_terms[DDIM * BATCH * DDIM];          // 67 MB (j,b,d) fp16
__device__ __half g_w2h [DDIM * DDIM * HDIM];            // 16.8 MB (j,d,h) fp16

// ======================= helpers ==========================================
__device__ __forceinline__ uint32_t smem_u32(const void* p) {
    uint32_t a;
    asm("{ .reg .u64 t; cvta.to.shared.u64 t, %1; cvt.u32.u64 %0, t; }"
        : "=r"(a) : "l"(p));
    return a;
}
__device__ __forceinline__ uint32_t pack2h(float a, float b) {
    __half2 t = __floats2half2_rn(a, b);
    return *reinterpret_cast<uint32_t*>(&t);
}
// fast tanh: sign(x) * (1 - 2/(1+e^{2|x|})). EX2+RCP based, overflow-safe.
__device__ __forceinline__ float fast_tanh(float x) {
    float ax = fabsf(x);
    float e  = __expf(2.f * ax);
    float r  = 1.f - __fdividef(2.f, 1.f + e);
    return copysignf(r, x);
}
// 128B-row swizzle: XOR byte-col bits[6:4] with (row&7)<<4 (bijective per row)
__device__ __forceinline__ uint32_t sw_off(int row, int colb) {
    return (uint32_t)(row * 128 + (colb ^ ((row & 7) << 4)));
}
#define LDSM_X4(r0, r1, r2, r3, addr)                                          \
    asm volatile("ldmatrix.sync.aligned.m8n8.x4.shared.b16 {%0,%1,%2,%3}, [%4];" \
                 : "=r"(r0), "=r"(r1), "=r"(r2), "=r"(r3) : "r"(addr))
#define MMA_FP16(d, a, b)                                                      \
    asm volatile("mma.sync.aligned.m16n8k16.row.col.f32.f16.f16.f32 "          \
                 "{%0,%1,%2,%3}, {%4,%5,%6,%7}, {%8,%9}, {%0,%1,%2,%3};"       \
                 : "+f"((d)[0]), "+f"((d)[1]), "+f"((d)[2]), "+f"((d)[3])      \
                 : "r"((a)[0]), "r"((a)[1]), "r"((a)[2]), "r"((a)[3]),         \
                   "r"((b)[0]), "r"((b)[1]))
#define CP_ASYNC16(saddr, gptr)                                                \
    asm volatile("cp.async.cg.shared.global [%0], [%1], 16;"                   \
                 :: "r"(saddr), "l"(gptr) : "memory")
#define CP_COMMIT()  asm volatile("cp.async.commit_group;" ::: "memory")
#define CP_WAIT1()   asm volatile("cp.async.wait_group 1;" ::: "memory")
#define CP_WAIT0()   asm volatile("cp.async.wait_group 0;" ::: "memory")

// ------- kernel 1: fused [W2 fp32->fp16 convert] + [encoder gemm1] --------
#define GEMM1_BLOCKS 256
#define CVT_BLOCKS   (DDIM * DDIM * HDIM / 4 / 256)     // 8192

__global__ void fused_cvt_gemm1(const float* __restrict__ A,
                                const float* __restrict__ Bw,
                                const float* __restrict__ bias,
                                float* __restrict__ C,
                                const float4* __restrict__ w2,
                                uint2* __restrict__ w2h)
{
    __shared__ __align__(16) float As[32][68];
    __shared__ __align__(16) float Bs[32][68];

    const int t = threadIdx.x;

    if (blockIdx.x >= GEMM1_BLOCKS) {
        int i = (blockIdx.x - GEMM1_BLOCKS) * 256 + t;
        float4 v = w2[i];
        uint2 H;
        H.x = pack2h(v.x, v.y);
        H.y = pack2h(v.z, v.w);
        w2h[i] = H;
        return;
    }

    // gemm1: M=2048, N=512, K=128, leaky
    const int N = HDIM, K = DDIM;
    const int m0 = (blockIdx.x & 31) * 64;
    const int n0 = (blockIdx.x >> 5) * 64;
    const int mg = t >> 4;
    const int ng = t & 15;

    float acc[4][4] = {};

    for (int k0 = 0; k0 < K; k0 += 32) {
        __syncthreads();
#pragma unroll
        for (int i = 0; i < 8; i++) {
            int idx = i * 256 + t;
            int m = idx >> 5, k = idx & 31;
            As[k][m] = A [(size_t)(m0 + m) * K + k0 + k];
            Bs[k][m] = Bw[(size_t)(n0 + m) * K + k0 + k];
        }
        __syncthreads();
#pragma unroll
        for (int k = 0; k < 32; k++) {
            float4 av = *(const float4*)&As[k][mg * 4];
            float4 bv = *(const float4*)&Bs[k][ng * 4];
            float a[4] = {av.x, av.y, av.z, av.w};
            float b[4] = {bv.x, bv.y, bv.z, bv.w};
#pragma unroll
            for (int i = 0; i < 4; i++)
#pragma unroll
                for (int jj = 0; jj < 4; jj++)
                    acc[i][jj] = fmaf(a[i], b[jj], acc[i][jj]);
        }
    }

#pragma unroll
    for (int i = 0; i < 4; i++) {
        int m = m0 + mg * 4 + i;
#pragma unroll
        for (int jj = 0; jj < 4; jj++) {
            int n = n0 + ng * 4 + jj;
            float c = acc[i][jj] + bias[n];
            C[(size_t)m * N + n] = fmaxf(c, 0.2f * c);
        }
    }
}

// ---------------- kernel 2: gemm2 (32x64 tiles -> 128 CTAs) ---------------
__global__ void gemm2_tanh(const float* __restrict__ A,
                           const float* __restrict__ Bw,
                           const float* __restrict__ bias,
                           float* __restrict__ C)
{
    __shared__ __align__(16) float As[32][36];
    __shared__ __align__(16) float Bs[32][68];

    const int N = DDIM, K = HDIM;
    const int t  = threadIdx.x;
    const int m0 = blockIdx.x * 32;
    const int n0 = blockIdx.y * 64;
    const int mg = t >> 4;
    const int ng = t & 15;

    float acc[2][4] = {};

    for (int k0 = 0; k0 < K; k0 += 32) {
        __syncthreads();
#pragma unroll
        for (int i = 0; i < 4; i++) {
            int idx = i * 256 + t;
            int m = idx >> 5, k = idx & 31;
            As[k][m] = A[(size_t)(m0 + m) * K + k0 + k];
        }
#pragma unroll
        for (int i = 0; i < 8; i++) {
            int idx = i * 256 + t;
            int n = idx >> 5, k = idx & 31;
            Bs[k][n] = Bw[(size_t)(n0 + n) * K + k0 + k];
        }
        __syncthreads();
#pragma unroll
        for (int k = 0; k < 32; k++) {
            float2 av = *(const float2*)&As[k][mg * 2];
            float4 bv = *(const float4*)&Bs[k][ng * 4];
            float a[2] = {av.x, av.y};
            float b[4] = {bv.x, bv.y, bv.z, bv.w};
#pragma unroll
            for (int i = 0; i < 2; i++)
#pragma unroll
                for (int jj = 0; jj < 4; jj++)
                    acc[i][jj] = fmaf(a[i], b[jj], acc[i][jj]);
        }
    }

#pragma unroll
    for (int i = 0; i < 2; i++) {
        int m = m0 + mg * 2 + i;
#pragma unroll
        for (int jj = 0; jj < 4; jj++) {
            int n = n0 + ng * 4 + jj;
            C[(size_t)m * N + n] = fast_tanh(acc[i][jj] + bias[n]);
        }
    }
}

// ---------------- kernel 3: terms via mma.sync fp16 ------------------------
// CTA tile: M=128 x N=128, K=512 in 8 chunks of 64. Grid 2048 CTAs.
// 8 warps in 2(m) x 4(n), warp tile 64x32.
// A double-buffered (distance 1), B TRIPLE-buffered (prefetch distance 2).
#define KC 64
#define NCHUNK (HDIM / KC)                // 8
#define SM_Z     0
#define SM_W1    512
#define SM_B1    2560
#define SM_TILE0 4608
#define MAT_SZ   16384                    // 128 x 64 fp16
#define S_A(b)   (SM_TILE0 + (b) * MAT_SZ)
#define S_B(s)   (SM_TILE0 + 2 * MAT_SZ + (s) * MAT_SZ)
#define SMEM_TOTAL (SM_TILE0 + 5 * MAT_SZ)   // 86528 B -> 2 CTAs/SM

__global__ __launch_bounds__(256, 2)
void terms_mma_kernel(const float* __restrict__ encoded,
                      const float* __restrict__ W1s,
                      const float* __restrict__ b1s,
                      const __half* __restrict__ w2h,
                      __half* __restrict__ terms)
{
    extern __shared__ __align__(128) char smem[];
    const uint32_t sbase = smem_u32(smem);
    const int t   = threadIdx.x;
    const int l   = t & 31;
    const int wid = t >> 5;
    const int j   = blockIdx.y;
    const int b0  = blockIdx.x * 128;

    float* z_s  = (float*)(smem + SM_Z);
    float* w1_s = (float*)(smem + SM_W1);
    float* b1_s = (float*)(smem + SM_B1);

    w1_s[t]       = W1s[(size_t)j * HDIM + t];
    w1_s[t + 256] = W1s[(size_t)j * HDIM + t + 256];
    b1_s[t]       = b1s[(size_t)j * HDIM + t];
    b1_s[t + 256] = b1s[(size_t)j * HDIM + t + 256];
    if (t < 128) z_s[t] = encoded[(size_t)(b0 + t) * DDIM + j];
    __syncthreads();

    const int m0 = (wid & 1) * 64;
    const int n0 = (wid >> 1) * 32;
    const int ar  = ((l >> 3) & 1) * 8 + (l & 7);
    const int ac2 = (l >> 4) * 16;
    const uint32_t swA = (uint32_t)((ar & 7) << 4);
    const int br  = (l >> 4) * 8 + (l & 7);
    const int bc2 = ((l >> 3) & 1) * 16;
    const uint32_t swB = (uint32_t)((br & 7) << 4);
    const int pb  = t & 127;
    const int pk  = (t >> 7) * 32;
    const float z = z_s[pb];
    const int bseg = t & 7;
    const int bd0  = t >> 3;

    float acc[4][4][4] = {};

    auto loadB = [&](int c, int s) {
        const int hc = c * KC;
#pragma unroll
        for (int p = 0; p < 4; ++p) {
            const int d = p * 32 + bd0;
            const size_t goff = ((size_t)j * DDIM + d) * HDIM + hc + bseg * 8;
            CP_ASYNC16(sbase + S_B(s) + sw_off(d, bseg * 16), w2h + goff);
        }
    };
    auto storeA = [&](int c, int buf) {
        const int hc = c * KC;
#pragma unroll
        for (int i = 0; i < 4; ++i) {
            const int h = pk + i * 8;
            float v[8];
#pragma unroll
            for (int q = 0; q < 8; ++q) {
                float u = fmaf(z, w1_s[hc + h + q], b1_s[hc + h + q]);
                v[q] = fmaxf(u, 0.2f * u);
            }
            uint4 H;
            H.x = pack2h(v[0], v[1]); H.y = pack2h(v[2], v[3]);
            H.z = pack2h(v[4], v[5]); H.w = pack2h(v[6], v[7]);
            *(uint4*)(smem + S_A(buf) + sw_off(pb, h * 2)) = H;
        }
    };

    auto hmma = [&](int abuf, int bsel) {
        const uint32_t aB = sbase + S_A(abuf);
        const uint32_t bB = sbase + S_B(bsel);
#pragma unroll
        for (int ks = 0; ks < KC / 16; ++ks) {
            const int kb = ks * 32;
            uint32_t bf[4][2];
#pragma unroll
            for (int np = 0; np < 2; ++np) {
                const uint32_t ro = (uint32_t)((n0 + np * 16 + br) * 128);
                const uint32_t co = (uint32_t)(kb + bc2) ^ swB;
                LDSM_X4(bf[np*2][0], bf[np*2][1], bf[np*2+1][0], bf[np*2+1][1],
                        bB + ro + co);
            }
#pragma unroll
            for (int mt = 0; mt < 4; ++mt) {
                const uint32_t ro = (uint32_t)((m0 + mt * 16 + ar) * 128);
                const uint32_t co = (uint32_t)(kb + ac2) ^ swA;
                uint32_t af[4];
                LDSM_X4(af[0], af[1], af[2], af[3], aB + ro + co);
#pragma unroll
                for (int nt = 0; nt < 4; ++nt)
                    MMA_FP16(acc[mt][nt], af, bf[nt]);
            }
        }
    };

    // ---- pipeline: B prefetch distance 2 (triple buffer), A distance 1 ----
    loadB(0, 0); CP_COMMIT();
    loadB(1, 1); CP_COMMIT();
    storeA(0, 0);
    CP_WAIT1();                 // B(0) complete, B(1) in flight
    __syncthreads();

    for (int c = 0; c < NCHUNK; ++c) {
        if (c + 2 < NCHUNK) { loadB(c + 2, (c + 2) % 3); CP_COMMIT(); }
        if (c + 1 < NCHUNK) storeA(c + 1, (c + 1) & 1);
        hmma(c & 1, c % 3);
        if (c + 1 < NCHUNK) {
            if (c + 2 < NCHUNK) CP_WAIT1(); else CP_WAIT0();
            __syncthreads();    // A(c+1)/B(c+1) visible; chunk c reads done
        }
    }

    // ---- epilogue: fp16 packed stores ----
    const int t4 = l >> 2, tn = (l & 3) * 2;
#pragma unroll
    for (int mt = 0; mt < 4; ++mt) {
        const int row0 = b0 + m0 + mt * 16 + t4;
        __half* p0 = terms + ((size_t)j * BATCH + row0) * DDIM;
        __half* p1 = terms + ((size_t)j * BATCH + row0 + 8) * DDIM;
#pragma unroll
        for (int nt = 0; nt < 4; ++nt) {
            const int col = n0 + nt * 8 + tn;
            *(uint32_t*)&p0[col] = pack2h(acc[mt][nt][0], acc[mt][nt][1]);
            *(uint32_t*)&p1[col] = pack2h(acc[mt][nt][2], acc[mt][nt][3]);
        }
    }
}

// ---------------- kernel 4: cumsum over j + bias + tanh --------------------
// One half2 column per thread -> 131072 threads / 512 CTAs. Unroll 16 for MLP.
__global__ __launch_bounds__(256)
void cumsum_tanh(const __half* __restrict__ terms,
                 const float* __restrict__ b2s,
                 float* __restrict__ out)
{
    const int g  = blockIdx.x * 256 + threadIdx.x;    // 0..131071
    const int dq = g & 63;                            // half2 index within d
    const size_t jstride = (size_t)BATCH * DDIM / 2;  // 2-elem units per level

    const __half2* tp = (const __half2*)terms + g;
    float2*        op = (float2*)out + g;
    const float2*  bp = (const float2*)b2s + dq;

    float2 acc = make_float2(0.f, 0.f);
#pragma unroll 16
    for (int j = 0; j < DDIM; j++) {
        float2 tv = __half22float2(tp[(size_t)j * jstride]);
        float2 bv = bp[(size_t)j * (DDIM / 2)];
        acc.x += tv.x + bv.x;
        acc.y += tv.y + bv.y;
        op[(size_t)j * jstride] = make_float2(fast_tanh(acc.x), fast_tanh(acc.y));
    }
}

// ---------------- launch ---------------------------------------------------
extern "C" void kernel_launch(void* const* d_in, const int* in_sizes, int n_in,
                              void* d_out, int out_size)
{
    const float* x   = (const float*)d_in[0];
    const float* We1 = (const float*)d_in[1];
    const float* be1 = (const float*)d_in[2];
    const float* We2 = (const float*)d_in[3];
    const float* be2 = (const float*)d_in[4];
    const float* W1s = (const float*)d_in[5];
    const float* b1s = (const float*)d_in[6];
    const float* W2s = (const float*)d_in[7];
    const float* b2s = (const float*)d_in[8];
    float* out = (float*)d_out;

    float *ench, *enc;
    __half *terms, *w2h;
    cudaGetSymbolAddress((void**)&ench,  g_ench);
    cudaGetSymbolAddress((void**)&enc,   g_enc);
    cudaGetSymbolAddress((void**)&terms, g_terms);
    cudaGetSymbolAddress((void**)&w2h,   g_w2h);

    cudaFuncSetAttribute(terms_mma_kernel,
                         cudaFuncAttributeMaxDynamicSharedMemorySize, SMEM_TOTAL);

    // fused: W2 convert + encoder gemm1 in one launch
    fused_cvt_gemm1<<<GEMM1_BLOCKS + CVT_BLOCKS, 256>>>(
        x, We1, be1, ench, (const float4*)W2s, (uint2*)w2h);

    // encoder gemm2 (32x64 tiles, 128 CTAs)
    gemm2_tanh<<<dim3(BATCH / 32, DDIM / 64), 256>>>(ench, We2, be2, enc);

    // terms via fp16 HMMA (8 warps, B prefetch distance 2)
    terms_mma_kernel<<<dim3(BATCH / 128, DDIM), 256, SMEM_TOTAL>>>(
        enc, W1s, b1s, w2h, terms);

    // cumsum + bias + fast tanh (fp16 terms in, fp32 out)
    cumsum_tanh<<<(BATCH * DDIM / 2) / 256, 256>>>(terms, b2s, out);
}

// round 15
// speedup vs baseline: 1.0080x; 1.0080x over previous
#include <cuda_runtime.h>
#include <cuda_fp16.h>
#include <math.h>
#include <stdint.h>

// Shapes (fixed): B=2048, D=128, H=512
#define BATCH 2048
#define DDIM  128
#define HDIM  512

// ---------------- device scratch (static; no allocations) ----------------
__device__ float g_ench [BATCH * HDIM];                  // 4 MB
__device__ float g_enc  [BATCH * DDIM];                  // 1 MB
__device__ __half g_terms[DDIM * BATCH * DDIM];          // 67 MB (j,b,d) fp16
__device__ __half g_w2h [DDIM * DDIM * HDIM];            // 16.8 MB (j,d,h) fp16

// ======================= helpers ==========================================
__device__ __forceinline__ uint32_t smem_u32(const void* p) {
    uint32_t a;
    asm("{ .reg .u64 t; cvta.to.shared.u64 t, %1; cvt.u32.u64 %0, t; }"
        : "=r"(a) : "l"(p));
    return a;
}
__device__ __forceinline__ uint32_t pack2h(float a, float b) {
    __half2 t = __floats2half2_rn(a, b);
    return *reinterpret_cast<uint32_t*>(&t);
}
// fast tanh: sign(x) * (1 - 2/(1+e^{2|x|})). EX2+RCP based, overflow-safe.
__device__ __forceinline__ float fast_tanh(float x) {
    float ax = fabsf(x);
    float e  = __expf(2.f * ax);
    float r  = 1.f - __fdividef(2.f, 1.f + e);
    return copysignf(r, x);
}
// 128B-row swizzle: XOR byte-col bits[6:4] with (row&7)<<4 (bijective per row)
__device__ __forceinline__ uint32_t sw_off(int row, int colb) {
    return (uint32_t)(row * 128 + (colb ^ ((row & 7) << 4)));
}
#define LDSM_X4(r0, r1, r2, r3, addr)                                          \
    asm volatile("ldmatrix.sync.aligned.m8n8.x4.shared.b16 {%0,%1,%2,%3}, [%4];" \
                 : "=r"(r0), "=r"(r1), "=r"(r2), "=r"(r3) : "r"(addr))
#define MMA_FP16(d, a, b)                                                      \
    asm volatile("mma.sync.aligned.m16n8k16.row.col.f32.f16.f16.f32 "          \
                 "{%0,%1,%2,%3}, {%4,%5,%6,%7}, {%8,%9}, {%0,%1,%2,%3};"       \
                 : "+f"((d)[0]), "+f"((d)[1]), "+f"((d)[2]), "+f"((d)[3])      \
                 : "r"((a)[0]), "r"((a)[1]), "r"((a)[2]), "r"((a)[3]),         \
                   "r"((b)[0]), "r"((b)[1]))
#define CP_ASYNC16(saddr, gptr)                                                \
    asm volatile("cp.async.cg.shared.global [%0], [%1], 16;"                   \
                 :: "r"(saddr), "l"(gptr) : "memory")
#define CP_COMMIT()  asm volatile("cp.async.commit_group;" ::: "memory")
#define CP_WAIT0()   asm volatile("cp.async.wait_group 0;" ::: "memory")

// half of the cvt work rides with each encoder launch
#define CVT_HALF_BLOCKS (DDIM * DDIM * HDIM / 4 / 256 / 2)   // 4096

__device__ __forceinline__ void cvt_block(int cb, const float4* w2, uint2* w2h,
                                          int t) {
    int i = cb * 256 + t;
    float4 v = w2[i];
    uint2 H;
    H.x = pack2h(v.x, v.y);
    H.y = pack2h(v.z, v.w);
    w2h[i] = H;
}

// ------- kernel 1: fused [W2 cvt first half] + [encoder gemm1] ------------
#define GEMM1_BLOCKS 256

__global__ void fused_cvt_gemm1(const float* __restrict__ A,
                                const float* __restrict__ Bw,
                                const float* __restrict__ bias,
                                float* __restrict__ C,
                                const float4* __restrict__ w2,
                                uint2* __restrict__ w2h)
{
    __shared__ __align__(16) float As[32][68];
    __shared__ __align__(16) float Bs[32][68];

    const int t = threadIdx.x;

    if (blockIdx.x >= GEMM1_BLOCKS) {
        cvt_block(blockIdx.x - GEMM1_BLOCKS, w2, w2h, t);
        return;
    }

    // gemm1: M=2048, N=512, K=128, leaky
    const int N = HDIM, K = DDIM;
    const int m0 = (blockIdx.x & 31) * 64;
    const int n0 = (blockIdx.x >> 5) * 64;
    const int mg = t >> 4;
    const int ng = t & 15;

    float acc[4][4] = {};

    for (int k0 = 0; k0 < K; k0 += 32) {
        __syncthreads();
#pragma unroll
        for (int i = 0; i < 8; i++) {
            int idx = i * 256 + t;
            int m = idx >> 5, k = idx & 31;
            As[k][m] = A [(size_t)(m0 + m) * K + k0 + k];
            Bs[k][m] = Bw[(size_t)(n0 + m) * K + k0 + k];
        }
        __syncthreads();
#pragma unroll
        for (int k = 0; k < 32; k++) {
            float4 av = *(const float4*)&As[k][mg * 4];
            float4 bv = *(const float4*)&Bs[k][ng * 4];
            float a[4] = {av.x, av.y, av.z, av.w};
            float b[4] = {bv.x, bv.y, bv.z, bv.w};
#pragma unroll
            for (int i = 0; i < 4; i++)
#pragma unroll
                for (int jj = 0; jj < 4; jj++)
                    acc[i][jj] = fmaf(a[i], b[jj], acc[i][jj]);
        }
    }

#pragma unroll
    for (int i = 0; i < 4; i++) {
        int m = m0 + mg * 4 + i;
#pragma unroll
        for (int jj = 0; jj < 4; jj++) {
            int n = n0 + ng * 4 + jj;
            float c = acc[i][jj] + bias[n];
            C[(size_t)m * N + n] = fmaxf(c, 0.2f * c);
        }
    }
}

// ------- kernel 2: fused [W2 cvt second half] + [gemm2 tanh] ---------------
#define GEMM2_BLOCKS 128   // (2048/32) x (128/64) flattened

__global__ void fused_cvt_gemm2(const float* __restrict__ A,
                                const float* __restrict__ Bw,
                                const float* __restrict__ bias,
                                float* __restrict__ C,
                                const float4* __restrict__ w2,
                                uint2* __restrict__ w2h)
{
    __shared__ __align__(16) float As[32][36];
    __shared__ __align__(16) float Bs[32][68];

    const int t = threadIdx.x;

    if (blockIdx.x >= GEMM2_BLOCKS) {
        cvt_block(CVT_HALF_BLOCKS + (blockIdx.x - GEMM2_BLOCKS), w2, w2h, t);
        return;
    }

    // gemm2: M=2048, N=128, K=512, tanh. 32x64 tiles.
    const int N = DDIM, K = HDIM;
    const int m0 = (blockIdx.x & 63) * 32;
    const int n0 = (blockIdx.x >> 6) * 64;
    const int mg = t >> 4;
    const int ng = t & 15;

    float acc[2][4] = {};

    for (int k0 = 0; k0 < K; k0 += 32) {
        __syncthreads();
#pragma unroll
        for (int i = 0; i < 4; i++) {
            int idx = i * 256 + t;
            int m = idx >> 5, k = idx & 31;
            As[k][m] = A[(size_t)(m0 + m) * K + k0 + k];
        }
#pragma unroll
        for (int i = 0; i < 8; i++) {
            int idx = i * 256 + t;
            int n = idx >> 5, k = idx & 31;
            Bs[k][n] = Bw[(size_t)(n0 + n) * K + k0 + k];
        }
        __syncthreads();
#pragma unroll
        for (int k = 0; k < 32; k++) {
            float2 av = *(const float2*)&As[k][mg * 2];
            float4 bv = *(const float4*)&Bs[k][ng * 4];
            float a[2] = {av.x, av.y};
            float b[4] = {bv.x, bv.y, bv.z, bv.w};
#pragma unroll
            for (int i = 0; i < 2; i++)
#pragma unroll
                for (int jj = 0; jj < 4; jj++)
                    acc[i][jj] = fmaf(a[i], b[jj], acc[i][jj]);
        }
    }

#pragma unroll
    for (int i = 0; i < 2; i++) {
        int m = m0 + mg * 2 + i;
#pragma unroll
        for (int jj = 0; jj < 4; jj++) {
            int n = n0 + ng * 4 + jj;
            C[(size_t)m * N + n] = fast_tanh(acc[i][jj] + bias[n]);
        }
    }
}

// ---------------- kernel 3: terms via mma.sync fp16 (R9 schedule) ----------
// CTA tile: M=128 x N=128, K=512 in 8 chunks of 64. Grid 2048 CTAs.
// 8 warps in 2(m) x 4(n), warp tile 64x32. Double A + double B, 1 sync/chunk.
#define KC 64
#define SM_Z     0
#define SM_W1    512
#define SM_B1    2560
#define SM_TILE0 4608
#define MAT_SZ   16384                    // 128 x 64 fp16
#define S_A(b)   (SM_TILE0 + (b) * MAT_SZ)
#define S_B(b)   (SM_TILE0 + 2 * MAT_SZ + (b) * MAT_SZ)
#define SMEM_TOTAL (SM_TILE0 + 4 * MAT_SZ)   // 70144 B -> 2 CTAs/SM

__global__ __launch_bounds__(256, 2)
void terms_mma_kernel(const float* __restrict__ encoded,
                      const float* __restrict__ W1s,
                      const float* __restrict__ b1s,
                      const __half* __restrict__ w2h,
                      __half* __restrict__ terms)
{
    extern __shared__ __align__(128) char smem[];
    const uint32_t sbase = smem_u32(smem);
    const int t   = threadIdx.x;
    const int l   = t & 31;
    const int wid = t >> 5;
    const int j   = blockIdx.y;
    const int b0  = blockIdx.x * 128;

    float* z_s  = (float*)(smem + SM_Z);
    float* w1_s = (float*)(smem + SM_W1);
    float* b1_s = (float*)(smem + SM_B1);

    w1_s[t]       = W1s[(size_t)j * HDIM + t];
    w1_s[t + 256] = W1s[(size_t)j * HDIM + t + 256];
    b1_s[t]       = b1s[(size_t)j * HDIM + t];
    b1_s[t + 256] = b1s[(size_t)j * HDIM + t + 256];
    if (t < 128) z_s[t] = encoded[(size_t)(b0 + t) * DDIM + j];
    __syncthreads();

    const int m0 = (wid & 1) * 64;
    const int n0 = (wid >> 1) * 32;
    const int ar  = ((l >> 3) & 1) * 8 + (l & 7);
    const int ac2 = (l >> 4) * 16;
    const uint32_t swA = (uint32_t)((ar & 7) << 4);
    const int br  = (l >> 4) * 8 + (l & 7);
    const int bc2 = ((l >> 3) & 1) * 16;
    const uint32_t swB = (uint32_t)((br & 7) << 4);
    const int pb  = t & 127;
    const int pk  = (t >> 7) * 32;
    const float z = z_s[pb];
    const int bseg = t & 7;
    const int bd0  = t >> 3;

    float acc[4][4][4] = {};

    auto loadB = [&](int c, int buf) {
        const int hc = c * KC;
#pragma unroll
        for (int p = 0; p < 4; ++p) {
            const int d = p * 32 + bd0;
            const size_t goff = ((size_t)j * DDIM + d) * HDIM + hc + bseg * 8;
            CP_ASYNC16(sbase + S_B(buf) + sw_off(d, bseg * 16), w2h + goff);
        }
    };
    auto storeA = [&](int c, int buf) {
        const int hc = c * KC;
#pragma unroll
        for (int i = 0; i < 4; ++i) {
            const int h = pk + i * 8;
            float v[8];
#pragma unroll
            for (int q = 0; q < 8; ++q) {
                float u = fmaf(z, w1_s[hc + h + q], b1_s[hc + h + q]);
                v[q] = fmaxf(u, 0.2f * u);
            }
            uint4 H;
            H.x = pack2h(v[0], v[1]); H.y = pack2h(v[2], v[3]);
            H.z = pack2h(v[4], v[5]); H.w = pack2h(v[6], v[7]);
            *(uint4*)(smem + S_A(buf) + sw_off(pb, h * 2)) = H;
        }
    };

    auto hmma = [&](int buf) {
        const uint32_t aB = sbase + S_A(buf);
        const uint32_t bB = sbase + S_B(buf);
#pragma unroll
        for (int ks = 0; ks < KC / 16; ++ks) {
            const int kb = ks * 32;
            uint32_t bf[4][2];
#pragma unroll
            for (int np = 0; np < 2; ++np) {
                const uint32_t ro = (uint32_t)((n0 + np * 16 + br) * 128);
                const uint32_t co = (uint32_t)(kb + bc2) ^ swB;
                LDSM_X4(bf[np*2][0], bf[np*2][1], bf[np*2+1][0], bf[np*2+1][1],
                        bB + ro + co);
            }
#pragma unroll
            for (int mt = 0; mt < 4; ++mt) {
                const uint32_t ro = (uint32_t)((m0 + mt * 16 + ar) * 128);
                const uint32_t co = (uint32_t)(kb + ac2) ^ swA;
                uint32_t af[4];
                LDSM_X4(af[0], af[1], af[2], af[3], aB + ro + co);
#pragma unroll
                for (int nt = 0; nt < 4; ++nt)
                    MMA_FP16(acc[mt][nt], af, bf[nt]);
            }
        }
    };

    loadB(0, 0);
    CP_COMMIT();
    storeA(0, 0);
    CP_WAIT0();
    __syncthreads();

    for (int c = 0; c < HDIM / KC; ++c) {
        const int cb = c & 1;
        if (c < HDIM / KC - 1) {
            loadB(c + 1, cb ^ 1);
            CP_COMMIT();
            storeA(c + 1, cb ^ 1);
        }
        hmma(cb);
        if (c < HDIM / KC - 1) {
            CP_WAIT0();
            __syncthreads();
        }
    }

    // ---- epilogue: fp16 packed stores ----
    const int t4 = l >> 2, tn = (l & 3) * 2;
#pragma unroll
    for (int mt = 0; mt < 4; ++mt) {
        const int row0 = b0 + m0 + mt * 16 + t4;
        __half* p0 = terms + ((size_t)j * BATCH + row0) * DDIM;
        __half* p1 = terms + ((size_t)j * BATCH + row0 + 8) * DDIM;
#pragma unroll
        for (int nt = 0; nt < 4; ++nt) {
            const int col = n0 + nt * 8 + tn;
            *(uint32_t*)&p0[col] = pack2h(acc[mt][nt][0], acc[mt][nt][1]);
            *(uint32_t*)&p1[col] = pack2h(acc[mt][nt][2], acc[mt][nt][3]);
        }
    }
}

// ---------------- kernel 4: cumsum over j + bias + tanh --------------------
// One HALF per thread -> 262144 threads / 1024 CTAs (~55% occ, 2x MLP chains).
__global__ __launch_bounds__(256)
void cumsum_tanh(const __half* __restrict__ terms,
                 const float* __restrict__ b2s,
                 float* __restrict__ out)
{
    const int g  = blockIdx.x * 256 + threadIdx.x;    // 0..262143
    const int dq = g & 127;                           // d index
    const size_t jstride = (size_t)BATCH * DDIM;      // elements per j level

    const __half* tp = terms + g;
    float*        op = out + g;
    const float*  bp = b2s + dq;

    float acc = 0.f;
#pragma unroll 16
    for (int j = 0; j < DDIM; j++) {
        float tv = __half2float(tp[(size_t)j * jstride]);
        float bv = bp[(size_t)j * DDIM];
        acc += tv + bv;
        op[(size_t)j * jstride] = fast_tanh(acc);
    }
}

// ---------------- launch ---------------------------------------------------
extern "C" void kernel_launch(void* const* d_in, const int* in_sizes, int n_in,
                              void* d_out, int out_size)
{
    const float* x   = (const float*)d_in[0];
    const float* We1 = (const float*)d_in[1];
    const float* be1 = (const float*)d_in[2];
    const float* We2 = (const float*)d_in[3];
    const float* be2 = (const float*)d_in[4];
    const float* W1s = (const float*)d_in[5];
    const float* b1s = (const float*)d_in[6];
    const float* W2s = (const float*)d_in[7];
    const float* b2s = (const float*)d_in[8];
    float* out = (float*)d_out;

    float *ench, *enc;
    __half *terms, *w2h;
    cudaGetSymbolAddress((void**)&ench,  g_ench);
    cudaGetSymbolAddress((void**)&enc,   g_enc);
    cudaGetSymbolAddress((void**)&terms, g_terms);
    cudaGetSymbolAddress((void**)&w2h,   g_w2h);

    cudaFuncSetAttribute(terms_mma_kernel,
                         cudaFuncAttributeMaxDynamicSharedMemorySize, SMEM_TOTAL);

    // encoder gemm1 + first half of W2 convert
    fused_cvt_gemm1<<<GEMM1_BLOCKS + CVT_HALF_BLOCKS, 256>>>(
        x, We1, be1, ench, (const float4*)W2s, (uint2*)w2h);

    // encoder gemm2 + second half of W2 convert
    fused_cvt_gemm2<<<GEMM2_BLOCKS + CVT_HALF_BLOCKS, 256>>>(
        ench, We2, be2, enc, (const float4*)W2s, (uint2*)w2h);

    // terms via fp16 HMMA (8 warps, R9 double-double schedule)
    terms_mma_kernel<<<dim3(BATCH / 128, DDIM), 256, SMEM_TOTAL>>>(
        enc, W1s, b1s, w2h, terms);

    // cumsum + bias + fast tanh (one half per thread)
    cumsum_tanh<<<(BATCH * DDIM) / 256, 256>>>(terms, b2s, out);
}

// round 16
// speedup vs baseline: 1.0488x; 1.0405x over previous
#include <cuda_runtime.h>
#include <cuda_fp16.h>
#include <math.h>
#include <stdint.h>

// Shapes (fixed): B=2048, D=128, H=512
#define BATCH 2048
#define DDIM  128
#define HDIM  512

// ---------------- device scratch (static; no allocations) ----------------
__device__ float g_ench [BATCH * HDIM];                  // 4 MB
__device__ float g_enc  [BATCH * DDIM];                  // 1 MB
__device__ __half g_terms[DDIM * BATCH * DDIM];          // 67 MB (j,b,d) fp16
__device__ __half g_w2h [DDIM * DDIM * HDIM];            // 16.8 MB (j,d,h) fp16

// ======================= helpers ==========================================
__device__ __forceinline__ uint32_t smem_u32(const void* p) {
    uint32_t a;
    asm("{ .reg .u64 t; cvta.to.shared.u64 t, %1; cvt.u32.u64 %0, t; }"
        : "=r"(a) : "l"(p));
    return a;
}
__device__ __forceinline__ uint32_t pack2h(float a, float b) {
    __half2 t = __floats2half2_rn(a, b);
    return *reinterpret_cast<uint32_t*>(&t);
}
// fast tanh: sign(x) * (1 - 2/(1+e^{2|x|})). EX2+RCP based, overflow-safe.
__device__ __forceinline__ float fast_tanh(float x) {
    float ax = fabsf(x);
    float e  = __expf(2.f * ax);
    float r  = 1.f - __fdividef(2.f, 1.f + e);
    return copysignf(r, x);
}
// 128B-row swizzle: XOR byte-col bits[6:4] with (row&7)<<4 (bijective per row)
__device__ __forceinline__ uint32_t sw_off(int row, int colb) {
    return (uint32_t)(row * 128 + (colb ^ ((row & 7) << 4)));
}
#define LDSM_X4(r0, r1, r2, r3, addr)                                          \
    asm volatile("ldmatrix.sync.aligned.m8n8.x4.shared.b16 {%0,%1,%2,%3}, [%4];" \
                 : "=r"(r0), "=r"(r1), "=r"(r2), "=r"(r3) : "r"(addr))
#define MMA_FP16(d, a, b)                                                      \
    asm volatile("mma.sync.aligned.m16n8k16.row.col.f32.f16.f16.f32 "          \
                 "{%0,%1,%2,%3}, {%4,%5,%6,%7}, {%8,%9}, {%0,%1,%2,%3};"       \
                 : "+f"((d)[0]), "+f"((d)[1]), "+f"((d)[2]), "+f"((d)[3])      \
                 : "r"((a)[0]), "r"((a)[1]), "r"((a)[2]), "r"((a)[3]),         \
                   "r"((b)[0]), "r"((b)[1]))
#define CP_ASYNC16(saddr, gptr)                                                \
    asm volatile("cp.async.cg.shared.global [%0], [%1], 16;"                   \
                 :: "r"(saddr), "l"(gptr) : "memory")
#define CP_COMMIT()  asm volatile("cp.async.commit_group;" ::: "memory")
#define CP_WAIT0()   asm volatile("cp.async.wait_group 0;" ::: "memory")

// half of the cvt work rides with each encoder launch
#define CVT_HALF_BLOCKS (DDIM * DDIM * HDIM / 4 / 256 / 2)   // 4096

__device__ __forceinline__ void cvt_block(int cb, const float4* w2, uint2* w2h,
                                          int t) {
    int i = cb * 256 + t;
    float4 v = w2[i];
    uint2 H;
    H.x = pack2h(v.x, v.y);
    H.y = pack2h(v.z, v.w);
    w2h[i] = H;
}

// ------- kernel 1: fused [W2 cvt first half] + [encoder gemm1] ------------
#define GEMM1_BLOCKS 256

__global__ void fused_cvt_gemm1(const float* __restrict__ A,
                                const float* __restrict__ Bw,
                                const float* __restrict__ bias,
                                float* __restrict__ C,
                                const float4* __restrict__ w2,
                                uint2* __restrict__ w2h)
{
    __shared__ __align__(16) float As[32][68];
    __shared__ __align__(16) float Bs[32][68];

    const int t = threadIdx.x;

    if (blockIdx.x >= GEMM1_BLOCKS) {
        cvt_block(blockIdx.x - GEMM1_BLOCKS, w2, w2h, t);
        return;
    }

    // gemm1: M=2048, N=512, K=128, leaky
    const int N = HDIM, K = DDIM;
    const int m0 = (blockIdx.x & 31) * 64;
    const int n0 = (blockIdx.x >> 5) * 64;
    const int mg = t >> 4;
    const int ng = t & 15;

    float acc[4][4] = {};

    for (int k0 = 0; k0 < K; k0 += 32) {
        __syncthreads();
#pragma unroll
        for (int i = 0; i < 8; i++) {
            int idx = i * 256 + t;
            int m = idx >> 5, k = idx & 31;
            As[k][m] = A [(size_t)(m0 + m) * K + k0 + k];
            Bs[k][m] = Bw[(size_t)(n0 + m) * K + k0 + k];
        }
        __syncthreads();
#pragma unroll
        for (int k = 0; k < 32; k++) {
            float4 av = *(const float4*)&As[k][mg * 4];
            float4 bv = *(const float4*)&Bs[k][ng * 4];
            float a[4] = {av.x, av.y, av.z, av.w};
            float b[4] = {bv.x, bv.y, bv.z, bv.w};
#pragma unroll
            for (int i = 0; i < 4; i++)
#pragma unroll
                for (int jj = 0; jj < 4; jj++)
                    acc[i][jj] = fmaf(a[i], b[jj], acc[i][jj]);
        }
    }

#pragma unroll
    for (int i = 0; i < 4; i++) {
        int m = m0 + mg * 4 + i;
#pragma unroll
        for (int jj = 0; jj < 4; jj++) {
            int n = n0 + ng * 4 + jj;
            float c = acc[i][jj] + bias[n];
            C[(size_t)m * N + n] = fmaxf(c, 0.2f * c);
        }
    }
}

// ------- kernel 2: fused [W2 cvt second half] + [gemm2 tanh] ---------------
#define GEMM2_BLOCKS 128   // (2048/32) x (128/64) flattened

__global__ void fused_cvt_gemm2(const float* __restrict__ A,
                                const float* __restrict__ Bw,
                                const float* __restrict__ bias,
                                float* __restrict__ C,
                                const float4* __restrict__ w2,
                                uint2* __restrict__ w2h)
{
    __shared__ __align__(16) float As[32][36];
    __shared__ __align__(16) float Bs[32][68];

    const int t = threadIdx.x;

    if (blockIdx.x >= GEMM2_BLOCKS) {
        cvt_block(CVT_HALF_BLOCKS + (blockIdx.x - GEMM2_BLOCKS), w2, w2h, t);
        return;
    }

    // gemm2: M=2048, N=128, K=512, tanh. 32x64 tiles.
    const int N = DDIM, K = HDIM;
    const int m0 = (blockIdx.x & 63) * 32;
    const int n0 = (blockIdx.x >> 6) * 64;
    const int mg = t >> 4;
    const int ng = t & 15;

    float acc[2][4] = {};

    for (int k0 = 0; k0 < K; k0 += 32) {
        __syncthreads();
#pragma unroll
        for (int i = 0; i < 4; i++) {
            int idx = i * 256 + t;
            int m = idx >> 5, k = idx & 31;
            As[k][m] = A[(size_t)(m0 + m) * K + k0 + k];
        }
#pragma unroll
        for (int i = 0; i < 8; i++) {
            int idx = i * 256 + t;
            int n = idx >> 5, k = idx & 31;
            Bs[k][n] = Bw[(size_t)(n0 + n) * K + k0 + k];
        }
        __syncthreads();
#pragma unroll
        for (int k = 0; k < 32; k++) {
            float2 av = *(const float2*)&As[k][mg * 2];
            float4 bv = *(const float4*)&Bs[k][ng * 4];
            float a[2] = {av.x, av.y};
            float b[4] = {bv.x, bv.y, bv.z, bv.w};
#pragma unroll
            for (int i = 0; i < 2; i++)
#pragma unroll
                for (int jj = 0; jj < 4; jj++)
                    acc[i][jj] = fmaf(a[i], b[jj], acc[i][jj]);
        }
    }

#pragma unroll
    for (int i = 0; i < 2; i++) {
        int m = m0 + mg * 2 + i;
#pragma unroll
        for (int jj = 0; jj < 4; jj++) {
            int n = n0 + ng * 4 + jj;
            C[(size_t)m * N + n] = fast_tanh(acc[i][jj] + bias[n]);
        }
    }
}

// ---------------- kernel 3: terms via mma.sync fp16 ------------------------
// CTA tile: M=128 x N=128, K=512 in 8 chunks of 64. Grid 2048 CTAs.
// 4 warps (128 threads) in 2(m) x 2(n), warp tile 64x64: LDSM traffic
// 96KB -> 64KB per chunk. __launch_bounds__(128,2): 256 regs (no spills),
// 2 CTAs/SM. R9 double-double schedule (1 sync/chunk).
#define KC 64
#define SM_Z     0
#define SM_W1    512
#define SM_B1    2560
#define SM_TILE0 4608
#define MAT_SZ   16384                    // 128 x 64 fp16
#define S_A(b)   (SM_TILE0 + (b) * MAT_SZ)
#define S_B(b)   (SM_TILE0 + 2 * MAT_SZ + (b) * MAT_SZ)
#define SMEM_TOTAL (SM_TILE0 + 4 * MAT_SZ)   // 70144 B -> 2 CTAs/SM

__global__ __launch_bounds__(128, 2)
void terms_mma_kernel(const float* __restrict__ encoded,
                      const float* __restrict__ W1s,
                      const float* __restrict__ b1s,
                      const __half* __restrict__ w2h,
                      __half* __restrict__ terms)
{
    extern __shared__ __align__(128) char smem[];
    const uint32_t sbase = smem_u32(smem);
    const int t   = threadIdx.x;           // 0..127
    const int l   = t & 31;
    const int wid = t >> 5;                // 0..3
    const int j   = blockIdx.y;
    const int b0  = blockIdx.x * 128;

    float* z_s  = (float*)(smem + SM_Z);
    float* w1_s = (float*)(smem + SM_W1);
    float* b1_s = (float*)(smem + SM_B1);

#pragma unroll
    for (int i = 0; i < 4; i++) {
        w1_s[t + i * 128] = W1s[(size_t)j * HDIM + t + i * 128];
        b1_s[t + i * 128] = b1s[(size_t)j * HDIM + t + i * 128];
    }
    z_s[t] = encoded[(size_t)(b0 + t) * DDIM + j];
    __syncthreads();

    const int m0 = (wid & 1) * 64;              // warp m origin (b)
    const int n0 = (wid >> 1) * 64;             // warp n origin (d)
    const int ar  = ((l >> 3) & 1) * 8 + (l & 7);
    const int ac2 = (l >> 4) * 16;
    const uint32_t swA = (uint32_t)((ar & 7) << 4);
    const int br  = (l >> 4) * 8 + (l & 7);
    const int bc2 = ((l >> 3) & 1) * 16;
    const uint32_t swB = (uint32_t)((br & 7) << 4);
    // A producer: thread t -> b row t, all 64 k of the chunk
    const int pb  = t;
    const float z = z_s[pb];
    // B producer: thread -> 8 d-rows x 16B segment
    const int bseg = t & 7;
    const int bd0  = t >> 3;                    // 0..15

    float acc[4][8][4] = {};

    auto loadB = [&](int c, int buf) {
        const int hc = c * KC;
#pragma unroll
        for (int p = 0; p < 8; ++p) {
            const int d = p * 16 + bd0;
            const size_t goff = ((size_t)j * DDIM + d) * HDIM + hc + bseg * 8;
            CP_ASYNC16(sbase + S_B(buf) + sw_off(d, bseg * 16), w2h + goff);
        }
    };
    auto storeA = [&](int c, int buf) {
        const int hc = c * KC;
#pragma unroll
        for (int i = 0; i < 8; ++i) {
            const int h = i * 8;
            float v[8];
#pragma unroll
            for (int q = 0; q < 8; ++q) {
                float u = fmaf(z, w1_s[hc + h + q], b1_s[hc + h + q]);
                v[q] = fmaxf(u, 0.2f * u);
            }
            uint4 H;
            H.x = pack2h(v[0], v[1]); H.y = pack2h(v[2], v[3]);
            H.z = pack2h(v[4], v[5]); H.w = pack2h(v[6], v[7]);
            *(uint4*)(smem + S_A(buf) + sw_off(pb, h * 2)) = H;
        }
    };

    auto hmma = [&](int buf) {
        const uint32_t aB = sbase + S_A(buf);
        const uint32_t bB = sbase + S_B(buf);
#pragma unroll
        for (int ks = 0; ks < KC / 16; ++ks) {
            const int kb = ks * 32;
            uint32_t bf[8][2];
#pragma unroll
            for (int np = 0; np < 4; ++np) {
                const uint32_t ro = (uint32_t)((n0 + np * 16 + br) * 128);
                const uint32_t co = (uint32_t)(kb + bc2) ^ swB;
                LDSM_X4(bf[np*2][0], bf[np*2][1], bf[np*2+1][0], bf[np*2+1][1],
                        bB + ro + co);
            }
#pragma unroll
            for (int mt = 0; mt < 4; ++mt) {
                const uint32_t ro = (uint32_t)((m0 + mt * 16 + ar) * 128);
                const uint32_t co = (uint32_t)(kb + ac2) ^ swA;
                uint32_t af[4];
                LDSM_X4(af[0], af[1], af[2], af[3], aB + ro + co);
#pragma unroll
                for (int nt = 0; nt < 8; ++nt)
                    MMA_FP16(acc[mt][nt], af, bf[nt]);
            }
        }
    };

    // ---- pipeline: double A + double B, one sync per chunk ----
    loadB(0, 0);
    CP_COMMIT();
    storeA(0, 0);
    CP_WAIT0();
    __syncthreads();

    for (int c = 0; c < HDIM / KC; ++c) {
        const int cb = c & 1;
        if (c < HDIM / KC - 1) {
            loadB(c + 1, cb ^ 1);
            CP_COMMIT();
            storeA(c + 1, cb ^ 1);
        }
        hmma(cb);
        if (c < HDIM / KC - 1) {
            CP_WAIT0();
            __syncthreads();
        }
    }

    // ---- epilogue: fp16 packed stores ----
    const int t4 = l >> 2, tn = (l & 3) * 2;
#pragma unroll
    for (int mt = 0; mt < 4; ++mt) {
        const int row0 = b0 + m0 + mt * 16 + t4;
        __half* p0 = terms + ((size_t)j * BATCH + row0) * DDIM;
        __half* p1 = terms + ((size_t)j * BATCH + row0 + 8) * DDIM;
#pragma unroll
        for (int nt = 0; nt < 8; ++nt) {
            const int col = n0 + nt * 8 + tn;
            *(uint32_t*)&p0[col] = pack2h(acc[mt][nt][0], acc[mt][nt][1]);
            *(uint32_t*)&p1[col] = pack2h(acc[mt][nt][2], acc[mt][nt][3]);
        }
    }
}

// ---------------- kernel 4: cumsum over j + bias + tanh (R14 config) -------
// One half2 column per thread -> 131072 threads / 512 CTAs. Unroll 16.
__global__ __launch_bounds__(256)
void cumsum_tanh(const __half* __restrict__ terms,
                 const float* __restrict__ b2s,
                 float* __restrict__ out)
{
    const int g  = blockIdx.x * 256 + threadIdx.x;    // 0..131071
    const int dq = g & 63;                            // half2 index within d
    const size_t jstride = (size_t)BATCH * DDIM / 2;  // 2-elem units per level

    const __half2* tp = (const __half2*)terms + g;
    float2*        op = (float2*)out + g;
    const float2*  bp = (const float2*)b2s + dq;

    float2 acc = make_float2(0.f, 0.f);
#pragma unroll 16
    for (int j = 0; j < DDIM; j++) {
        float2 tv = __half22float2(tp[(size_t)j * jstride]);
        float2 bv = bp[(size_t)j * (DDIM / 2)];
        acc.x += tv.x + bv.x;
        acc.y += tv.y + bv.y;
        op[(size_t)j * jstride] = make_float2(fast_tanh(acc.x), fast_tanh(acc.y));
    }
}

// ---------------- launch ---------------------------------------------------
extern "C" void kernel_launch(void* const* d_in, const int* in_sizes, int n_in,
                              void* d_out, int out_size)
{
    const float* x   = (const float*)d_in[0];
    const float* We1 = (const float*)d_in[1];
    const float* be1 = (const float*)d_in[2];
    const float* We2 = (const float*)d_in[3];
    const float* be2 = (const float*)d_in[4];
    const float* W1s = (const float*)d_in[5];
    const float* b1s = (const float*)d_in[6];
    const float* W2s = (const float*)d_in[7];
    const float* b2s = (const float*)d_in[8];
    float* out = (float*)d_out;

    float *ench, *enc;
    __half *terms, *w2h;
    cudaGetSymbolAddress((void**)&ench,  g_ench);
    cudaGetSymbolAddress((void**)&enc,   g_enc);
    cudaGetSymbolAddress((void**)&terms, g_terms);
    cudaGetSymbolAddress((void**)&w2h,   g_w2h);

    cudaFuncSetAttribute(terms_mma_kernel,
                         cudaFuncAttributeMaxDynamicSharedMemorySize, SMEM_TOTAL);

    // encoder gemm1 + first half of W2 convert
    fused_cvt_gemm1<<<GEMM1_BLOCKS + CVT_HALF_BLOCKS, 256>>>(
        x, We1, be1, ench, (const float4*)W2s, (uint2*)w2h);

    // encoder gemm2 + second half of W2 convert
    fused_cvt_gemm2<<<GEMM2_BLOCKS + CVT_HALF_BLOCKS, 256>>>(
        ench, We2, be2, enc, (const float4*)W2s, (uint2*)w2h);

    // terms via fp16 HMMA (4 warps, 64x64 warp tiles, 2 CTAs/SM, 256 regs)
    terms_mma_kernel<<<dim3(BATCH / 128, DDIM), 128, SMEM_TOTAL>>>(
        enc, W1s, b1s, w2h, terms);

    // cumsum + bias + fast tanh (half2 per thread, unroll 16)
    cumsum_tanh<<<(BATCH * DDIM / 2) / 256, 256>>>(terms, b2s, out);
}